// round 8
// baseline (speedup 1.0000x reference)
#include <cuda_runtime.h>
#include <math.h>
#include <stdint.h>

#define NV     12
#define BATCH  4096
#define DIM    128
#define ALPHA  0.4f
#define BETA   2.0f
#define LAMDA  2.0f

#define B_PER_BLK 2            // batch elements per block (2 warps each)
#define THREADS   128
#define NBLOCKS   (BATCH / B_PER_BLK)    // 2048
#define CHUNK     32           // k-dims per staged chunk
#define PITCH     36           // floats per smem row (32 data + 4 pad) = 144B
#define ROWS      24           // 12 A rows + 12 N rows
#define CBUF      (ROWS * PITCH)         // 864 floats per chunk buffer
#define NSTAGE    6            // float4 staged per lane per chunk

// Per-block partials + ticket (device globals, zero-initialized)
__device__ float g_pl[NBLOCKS];
__device__ float g_pc[NBLOCKS];
__device__ float g_pm[NBLOCKS];
__device__ float g_pa[NBLOCKS];
__device__ float g_pmin[NBLOCKS];
__device__ unsigned int g_ticket;

__device__ __forceinline__ float dot4(float4 a, float4 b) {
    return a.x * b.x + a.y * b.y + a.z * b.z + a.w * b.w;
}
__device__ __forceinline__ float sqdiff4(float4 a, float4 b) {
    float x = a.x - b.x, y = a.y - b.y, z = a.z - b.z, w = a.w - b.w;
    return x * x + y * y + z * z + w * w;
}
__device__ __forceinline__ void cp_async16(uint32_t saddr, const void* gptr) {
    asm volatile("cp.async.cg.shared.global [%0], [%1], 16;"
                 :: "r"(saddr), "l"(gptr));
}
#define CP_COMMIT()  asm volatile("cp.async.commit_group;")
#define CP_WAIT(N)   asm volatile("cp.async.wait_group %0;" :: "n"(N))

__global__ __launch_bounds__(THREADS)
void pil_fused(const float* __restrict__ SV_A, const float* __restrict__ SV_N,
               const float* __restrict__ MV_A, const float* __restrict__ MV_N,
               float* __restrict__ out, int out_size)
{
    // 4 warps x 2 chunk-buffers x 864 floats = 27648 B.
    // After the mainloop each warp reuses ITS OWN region for partials:
    //   G partial  at floats [0..143]   (16 lanes x 9)
    //   norm part. at floats [160..183] (24 rows)
    // The last-block reduction reuses the whole tile as scratch.
    __shared__ float tile[4 * 2 * CBUF];
    __shared__ float r_loss[B_PER_BLK], r_cnt[B_PER_BLK];
    __shared__ float r_mc[B_PER_BLK], r_ac[B_PER_BLK], r_mn[B_PER_BLK];
    __shared__ int   s_islast;

    const int tid  = threadIdx.x;
    const int lane = tid & 31;
    const int wrp  = tid >> 5;       // 0..3
    const int e    = wrp >> 1;       // local batch element 0..1
    const int kw   = wrp & 1;        // k-half: dims [kw*64, kw*64+64)
    const int h    = lane >> 4;      // 16-dim half within a 32-chunk
    const int t    = lane & 15;
    const int ti   = t >> 2;         // A rows 3*ti..3*ti+2
    const int tj   = t & 3;          // N rows 3*tj..3*tj+2
    const int bg   = blockIdx.x * B_PER_BLK + e;

    float* wbuf = &tile[wrp * 2 * CBUF];      // this warp's two chunk buffers
    const uint32_t wbase = (uint32_t)__cvta_generic_to_shared(wbuf);

    // ---- staging addresses: 6 float4 per lane per chunk (warp-local)
    const float* gsrc[NSTAGE];
    uint32_t     soff[NSTAGE];                 // byte offset within chunk buf
    #pragma unroll
    for (int s = 0; s < NSTAGE; ++s) {
        int f   = lane + 32 * s;               // 0..191
        int row = f >> 3;                      // 0..23
        int k4  = f & 7;
        const float* base = (row < NV)
            ? SV_A + ((size_t)row        * BATCH + bg) * DIM
            : SV_N + ((size_t)(row - NV) * BATCH + bg) * DIM;
        gsrc[s] = base + kw * 64 + k4 * 4;
        soff[s] = (uint32_t)((row * PITCH + k4 * 4) * 4);
    }

    // prologue: issue BOTH chunks of this warp's 64 dims (no refill needed)
    #pragma unroll
    for (int s = 0; s < NSTAGE; ++s)
        cp_async16(wbase + soff[s], gsrc[s]);
    CP_COMMIT();
    #pragma unroll
    for (int s = 0; s < NSTAGE; ++s)
        cp_async16(wbase + (uint32_t)(CBUF * 4) + soff[s], gsrc[s] + CHUNK);
    CP_COMMIT();

    float G[3][3] = {{0.f,0.f,0.f},{0.f,0.f,0.f},{0.f,0.f,0.f}};
    float nacc = 0.f;

    #pragma unroll
    for (int c = 0; c < 2; ++c) {
        if (c == 0) { CP_WAIT(1); } else { CP_WAIT(0); }
        __syncwarp();
        const float* tb = wbuf + c * CBUF;

        // ---- norm partial: lanes 0..23 each own one row (32 dims)
        if (lane < ROWS) {
            const float* rb = tb + lane * PITCH;
            float s0 = 0.f;
            #pragma unroll
            for (int k4 = 0; k4 < 8; ++k4) {
                float4 v = *reinterpret_cast<const float4*>(rb + k4 * 4);
                s0 += dot4(v, v);
            }
            nacc += s0;
        }

        // ---- 3x3 register-tiled Gram over this lane's 16-dim slice
        const float* A0 = tb + (3 * ti)      * PITCH + h * 16;
        const float* N0 = tb + (NV + 3 * tj) * PITCH + h * 16;
        #pragma unroll
        for (int k4 = 0; k4 < 4; ++k4) {
            float4 a0 = *reinterpret_cast<const float4*>(A0 + 0 * PITCH + k4 * 4);
            float4 a1 = *reinterpret_cast<const float4*>(A0 + 1 * PITCH + k4 * 4);
            float4 a2 = *reinterpret_cast<const float4*>(A0 + 2 * PITCH + k4 * 4);
            float4 n0 = *reinterpret_cast<const float4*>(N0 + 0 * PITCH + k4 * 4);
            float4 n1 = *reinterpret_cast<const float4*>(N0 + 1 * PITCH + k4 * 4);
            float4 n2 = *reinterpret_cast<const float4*>(N0 + 2 * PITCH + k4 * 4);
            G[0][0] += dot4(a0, n0); G[0][1] += dot4(a0, n1); G[0][2] += dot4(a0, n2);
            G[1][0] += dot4(a1, n0); G[1][1] += dot4(a1, n1); G[1][2] += dot4(a1, n2);
            G[2][0] += dot4(a2, n0); G[2][1] += dot4(a2, n1); G[2][2] += dot4(a2, n2);
        }
    }

    // ---- combine 16-dim halves within warp; lanes 0..15 hold 32-dim G
    #pragma unroll
    for (int r = 0; r < 3; ++r)
        #pragma unroll
        for (int cc = 0; cc < 3; ++cc)
            G[r][cc] += __shfl_xor_sync(0xffffffffu, G[r][cc], 16);

    // ---- publish this warp's partials into its own (dead) tile region
    __syncwarp();                 // all reads of wbuf done before overwrite
    if (h == 0) {
        #pragma unroll
        for (int r = 0; r < 3; ++r)
            #pragma unroll
            for (int cc = 0; cc < 3; ++cc)
                wbuf[t * 9 + r * 3 + cc] = G[r][cc];
    }
    if (lane < ROWS) wbuf[160 + lane] = nacc;
    __syncthreads();              // the single block-wide combine barrier

    // ---- warp kw==0 of each element finishes: G total, argmin, epilogue
    if (kw == 0) {
        const float* part0 = &tile[(e * 2 + 0) * 2 * CBUF];
        const float* part1 = &tile[(e * 2 + 1) * 2 * CBUF];

        float GT[3][3];
        #pragma unroll
        for (int r = 0; r < 3; ++r)
            #pragma unroll
            for (int cc = 0; cc < 3; ++cc)
                GT[r][cc] = part0[t * 9 + r * 3 + cc] + part1[t * 9 + r * 3 + cc];

        float dmin = 3.4e38f;
        int   imin = 0;
        #pragma unroll
        for (int r = 0; r < 3; ++r) {
            float na = part0[160 + 3 * ti + r] + part1[160 + 3 * ti + r];
            #pragma unroll
            for (int cc = 0; cc < 3; ++cc) {
                float nn = part0[160 + NV + 3 * tj + cc] + part1[160 + NV + 3 * tj + cc];
                float d  = na + nn - 2.f * GT[r][cc];
                int   fl = (3 * ti + r) * NV + (3 * tj + cc);
                if (d < dmin || (d == dmin && fl < imin)) { dmin = d; imin = fl; }
            }
        }
        #pragma unroll
        for (int o = 1; o < 16; o <<= 1) {   // halves hold identical data
            float od = __shfl_xor_sync(0xffffffffu, dmin, o);
            int   oi = __shfl_xor_sync(0xffffffffu, imin, o);
            if (od < dmin || (od == dmin && oi < imin)) { dmin = od; imin = oi; }
        }

        // ---- epilogue distances: 1 float4 per lane per array
        const int confA = imin / NV;
        const int confN = imin - confA * NV;

        float4 ma  = reinterpret_cast<const float4*>(MV_A + (size_t)bg * DIM)[lane];
        float4 mn_ = reinterpret_cast<const float4*>(MV_N + (size_t)bg * DIM)[lane];
        float4 fa  = reinterpret_cast<const float4*>(SV_A + ((size_t)confA * BATCH + bg) * DIM)[lane];
        float4 fn  = reinterpret_cast<const float4*>(SV_N + ((size_t)confN * BATCH + bg) * DIM)[lane];

        float smv = sqdiff4(ma, mn_);
        float sa  = sqdiff4(ma, fa);
        float sc  = sqdiff4(mn_, fn);
        #pragma unroll
        for (int o = 1; o < 32; o <<= 1) {
            smv += __shfl_xor_sync(0xffffffffu, smv, o);
            sa  += __shfl_xor_sync(0xffffffffu, sa,  o);
            sc  += __shfl_xor_sync(0xffffffffu, sc,  o);
        }

        if (lane == 0) {
            float mc       = fmaxf(dmin, 0.f);
            float mv_inter = sqrtf(smv);
            float a_cl     = sqrtf(sa);
            float c_in     = sqrtf(sc);
            float loss = LAMDA * (fmaxf(BETA - mc, 0.f) + fmaxf(BETA - mv_inter, 0.f))
                       + fmaxf(a_cl - ALPHA, 0.f) + fmaxf(c_in - ALPHA, 0.f);
            float sqmc = sqrtf(mc);
            r_loss[e] = loss;
            r_cnt[e]  = (loss != 0.f) ? 1.f : 0.f;
            r_mc[e]   = sqmc;
            r_ac[e]   = sqrtf(a_cl) + sqrtf(c_in);
            r_mn[e]   = sqmc;
        }
    }
    __syncthreads();

    // ---- per-block partial (fixed order -> deterministic) + ticket
    if (tid == 0) {
        float sl = 0.f, sn = 0.f, sm = 0.f, sa2 = 0.f, mn = 3.4e38f;
        #pragma unroll
        for (int i = 0; i < B_PER_BLK; ++i) {
            sl  += r_loss[i];
            sn  += r_cnt[i];
            sm  += r_mc[i];
            sa2 += r_ac[i];
            mn   = fminf(mn, r_mn[i]);
        }
        g_pl[blockIdx.x]   = sl;
        g_pc[blockIdx.x]   = sn;
        g_pm[blockIdx.x]   = sm;
        g_pa[blockIdx.x]   = sa2;
        g_pmin[blockIdx.x] = mn;
        __threadfence();
        unsigned int prev = atomicAdd(&g_ticket, 1u);
        s_islast = (prev == NBLOCKS - 1) ? 1 : 0;
    }
    __syncthreads();

    // ---- last block: deterministic final reduction over 2048 partials
    if (s_islast) {
        __threadfence();
        float (*red)[THREADS] = reinterpret_cast<float (*)[THREADS]>(tile);
        float al = 0.f, ac = 0.f, am = 0.f, aa = 0.f, amn = 3.4e38f;
        #pragma unroll
        for (int q = 0; q < NBLOCKS / THREADS; ++q) {   // 16, fixed order
            int i = tid + q * THREADS;
            al += g_pl[i];
            ac += g_pc[i];
            am += g_pm[i];
            aa += g_pa[i];
            amn = fminf(amn, g_pmin[i]);
        }
        red[0][tid] = al; red[1][tid] = ac; red[2][tid] = am;
        red[3][tid] = aa; red[4][tid] = amn;
        __syncthreads();
        for (int o = THREADS / 2; o > 0; o >>= 1) {
            if (tid < o) {
                red[0][tid] += red[0][tid + o];
                red[1][tid] += red[1][tid + o];
                red[2][tid] += red[2][tid + o];
                red[3][tid] += red[3][tid + o];
                red[4][tid]  = fminf(red[4][tid], red[4][tid + o]);
            }
            __syncthreads();
        }
        if (tid == 0) {
            const float inv = 1.f / (float)BATCH;
            if (out_size > 0) out[0] = red[0][0] * inv;          // avg_loss
            if (out_size > 1) out[1] = red[1][0];                // count_nonzero
            if (out_size > 2) out[2] = red[2][0] * inv;          // mean(sqrt(mc))
            if (out_size > 3) out[3] = 0.5f * red[3][0] * inv;   // cluster means
            if (out_size > 4) out[4] = red[4][0];                // min(sqrt(mc))
            for (int i = 5; i < out_size; ++i) out[i] = 0.f;
            g_ticket = 0;      // reset for next graph replay
        }
    }
}

extern "C" void kernel_launch(void* const* d_in, const int* in_sizes, int n_in,
                              void* d_out, int out_size)
{
    const float* SV_A = (const float*)d_in[0];
    const float* SV_N = (const float*)d_in[1];
    const float* MV_A = (const float*)d_in[2];
    const float* MV_N = (const float*)d_in[3];
    (void)in_sizes; (void)n_in;

    pil_fused<<<NBLOCKS, THREADS>>>(SV_A, SV_N, MV_A, MV_N,
                                    (float*)d_out, out_size);
}